// round 11
// baseline (speedup 1.0000x reference)
#include <cuda_runtime.h>
#include <cuda_fp16.h>
#include <math.h>
#include <stdint.h>

#define N_NODES 49998
#define E_EDGES 800000
#define DIN 128
#define NH0 8
#define DOUT 32
#define F0 (NH0 * DOUT)   // 256
#define F1 32
#define NE_PAIRS (N_NODES / 3)  // 16666
#define FULLMASK 0xffffffffu

// ---------------- scratch (device globals: no runtime alloc allowed) ----------------
__device__ __half g_f0h[N_NODES * F0];   // layer0 projected features (fp16)
__device__ __half g_hh[N_NODES * F0];    // elu(gat0 out) (fp16)
__device__ float g_el0[N_NODES * NH0];
__device__ float g_er0[N_NODES * NH0];
__device__ __half g_f1h[N_NODES * F1];   // layer1 projected features (fp16)
__device__ float g_el1[N_NODES];
__device__ float g_er1[N_NODES];
__device__ float g_h1[N_NODES * F1];
__device__ int   g_cnt[N_NODES];
__device__ int   g_rowptr[N_NODES + 1];
__device__ int   g_cur[N_NODES];
__device__ int   g_esrc[E_EDGES];

// ---------------- CSR build ----------------
__global__ void k_zero_cnt() {
    int i = blockIdx.x * blockDim.x + threadIdx.x;
    if (i < N_NODES) g_cnt[i] = 0;
}

__global__ void k_count(const int* __restrict__ dst) {
    int e = blockIdx.x * blockDim.x + threadIdx.x;
    if (e < E_EDGES) atomicAdd(&g_cnt[dst[e]], 1);
}

__global__ void k_scan() {
    const int T = 1024;
    int tid = threadIdx.x;
    int chunk = (N_NODES + T - 1) / T;
    int beg = tid * chunk;
    int end = beg + chunk; if (end > N_NODES) end = N_NODES;
    int s = 0;
    for (int i = beg; i < end; i++) s += g_cnt[i];
    __shared__ int sh[T];
    sh[tid] = s;
    __syncthreads();
    for (int d = 1; d < T; d <<= 1) {
        int v = (tid >= d) ? sh[tid - d] : 0;
        __syncthreads();
        sh[tid] += v;
        __syncthreads();
    }
    int run = sh[tid] - s;
    for (int i = beg; i < end; i++) {
        g_rowptr[i] = run;
        g_cur[i] = run;
        run += g_cnt[i];
    }
    if (tid == T - 1) g_rowptr[N_NODES] = sh[T - 1];
}

__global__ void k_fill(const int* __restrict__ src, const int* __restrict__ dst) {
    int e = blockIdx.x * blockDim.x + threadIdx.x;
    if (e < E_EDGES) {
        int p = atomicAdd(&g_cur[dst[e]], 1);
        g_esrc[p] = src[e];
    }
}

// ---------------- tf32 tensor-core GEMM (pipelined, double-buffered) ----------------
__device__ __forceinline__ uint32_t f2tf(float f) {
    uint32_t r;
    asm("cvt.rna.tf32.f32 %0, %1;" : "=r"(r) : "f"(f));
    return r;
}

__device__ __forceinline__ void mma_tf32(float* d, const uint32_t* a, const uint32_t* b) {
    asm volatile(
        "mma.sync.aligned.m16n8k8.row.col.f32.tf32.tf32.f32 "
        "{%0,%1,%2,%3},{%4,%5,%6,%7},{%8,%9},{%0,%1,%2,%3};\n"
        : "+f"(d[0]), "+f"(d[1]), "+f"(d[2]), "+f"(d[3])
        : "r"(a[0]), "r"(a[1]), "r"(a[2]), "r"(a[3]), "r"(b[0]), "r"(b[1]));
}

// C(MxNc) = A(MxK) @ B(KxNc), tf32 inputs, fp32 accumulate.
// HALF_IN: A is __half. HALF_OUT: C stored as __half.
// SCORES: fused el/er epilogue (needs WN==32).
template <int BM, int BN, int BK, int WM, int WN, int NH,
          bool SCORES, bool HALF_IN, bool HALF_OUT>
__global__ void k_gemm(const void* __restrict__ Av, const float* __restrict__ B,
                       void* __restrict__ Cv, int M, int Nc, int K,
                       const float* __restrict__ al, const float* __restrict__ ar,
                       float* __restrict__ el, float* __restrict__ er) {
    constexpr int WARPS_M = BM / WM;
    constexpr int WARPS_N = BN / WN;
    constexpr int THREADS = WARPS_M * WARPS_N * 32;
    constexpr int MT = WM / 16;
    constexpr int NT = WN / 8;
    constexpr int AP = BK + 4;
    constexpr int BP = BN + 8;
    constexpr int A_CG = BK / 4;                 // 4-elem col groups per A row
    constexpr int A_ROWS_PP = THREADS / A_CG;
    constexpr int A_PASSES = BM / A_ROWS_PP;
    constexpr int B_CG = BN / 4;
    constexpr int B_ROWS_PP = THREADS / B_CG;
    constexpr int B_PASSES = BK / B_ROWS_PP;
    static_assert(B_PASSES >= 1, "");

    __shared__ uint32_t As[2][BM][AP];
    __shared__ uint32_t Bs[2][BK][BP];

    const int tid = threadIdx.x;
    const int wid = tid >> 5, lane = tid & 31;
    const int wm = (wid / WARPS_N) * WM;
    const int wn = (wid % WARPS_N) * WN;
    const int g = lane >> 2, t = lane & 3;
    const int row0 = blockIdx.y * BM, col0 = blockIdx.x * BN;

    const int a_r = tid / A_CG;
    const int a_c = (tid % A_CG) * 4;
    const int b_r = tid / B_CG;
    const int b_c = (tid % B_CG) * 4;

    float apf[A_PASSES][4];
    float bpf[B_PASSES][4];

    float acc[MT][NT][4];
#pragma unroll
    for (int mt = 0; mt < MT; mt++)
#pragma unroll
        for (int nt = 0; nt < NT; nt++)
#pragma unroll
            for (int j = 0; j < 4; j++) acc[mt][nt][j] = 0.f;

    auto load_tiles = [&](int k0) {
#pragma unroll
        for (int p = 0; p < A_PASSES; p++) {
            int r = a_r + p * A_ROWS_PP;
            int gr = row0 + r;
            if (HALF_IN) {
                uint2 v = make_uint2(0u, 0u);
                if (gr < M)
                    v = *(const uint2*)((const __half*)Av + (long)gr * K + k0 * BK + a_c);
                float2 x0 = __half22float2(*(__half2*)&v.x);
                float2 x1 = __half22float2(*(__half2*)&v.y);
                apf[p][0] = x0.x; apf[p][1] = x0.y; apf[p][2] = x1.x; apf[p][3] = x1.y;
            } else {
                float4 v = make_float4(0.f, 0.f, 0.f, 0.f);
                if (gr < M)
                    v = *(const float4*)((const float*)Av + (long)gr * K + k0 * BK + a_c);
                apf[p][0] = v.x; apf[p][1] = v.y; apf[p][2] = v.z; apf[p][3] = v.w;
            }
        }
#pragma unroll
        for (int p = 0; p < B_PASSES; p++) {
            int r = b_r + p * B_ROWS_PP;
            float4 v = *(const float4*)&B[(long)(k0 * BK + r) * Nc + col0 + b_c];
            bpf[p][0] = v.x; bpf[p][1] = v.y; bpf[p][2] = v.z; bpf[p][3] = v.w;
        }
    };

    auto store_tiles = [&](int buf) {
#pragma unroll
        for (int p = 0; p < A_PASSES; p++) {
            int r = a_r + p * A_ROWS_PP;
            uint4 pk;
            pk.x = f2tf(apf[p][0]); pk.y = f2tf(apf[p][1]);
            pk.z = f2tf(apf[p][2]); pk.w = f2tf(apf[p][3]);
            *(uint4*)&As[buf][r][a_c] = pk;
        }
#pragma unroll
        for (int p = 0; p < B_PASSES; p++) {
            int r = b_r + p * B_ROWS_PP;
            uint4 pk;
            pk.x = f2tf(bpf[p][0]); pk.y = f2tf(bpf[p][1]);
            pk.z = f2tf(bpf[p][2]); pk.w = f2tf(bpf[p][3]);
            *(uint4*)&Bs[buf][r][b_c] = pk;
        }
    };

    auto compute = [&](int buf) {
#pragma unroll
        for (int ks = 0; ks < BK / 8; ks++) {
            const int k8 = ks * 8;
            uint32_t af[MT][4], bf[NT][2];
#pragma unroll
            for (int mt = 0; mt < MT; mt++) {
                int r = wm + mt * 16;
                af[mt][0] = As[buf][r + g][k8 + t];
                af[mt][1] = As[buf][r + g + 8][k8 + t];
                af[mt][2] = As[buf][r + g][k8 + t + 4];
                af[mt][3] = As[buf][r + g + 8][k8 + t + 4];
            }
#pragma unroll
            for (int nt = 0; nt < NT; nt++) {
                int c = wn + nt * 8 + g;
                bf[nt][0] = Bs[buf][k8 + t][c];
                bf[nt][1] = Bs[buf][k8 + t + 4][c];
            }
#pragma unroll
            for (int mt = 0; mt < MT; mt++)
#pragma unroll
                for (int nt = 0; nt < NT; nt++) mma_tf32(acc[mt][nt], af[mt], bf[nt]);
        }
    };

    const int KT = K / BK;
    load_tiles(0);
    store_tiles(0);
    __syncthreads();
    for (int k0 = 1; k0 < KT; k0++) {
        load_tiles(k0);             // global loads for next tile in flight
        compute((k0 - 1) & 1);      // compute current tile
        store_tiles(k0 & 1);
        __syncthreads();
    }
    compute((KT - 1) & 1);

    // store C
#pragma unroll
    for (int mt = 0; mt < MT; mt++) {
#pragma unroll
        for (int nt = 0; nt < NT; nt++) {
            int mr = row0 + wm + mt * 16 + g;
            int c = col0 + wn + nt * 8 + 2 * t;
            if (HALF_OUT) {
                __half* C = (__half*)Cv;
                if (mr < M)
                    *(__half2*)&C[(long)mr * Nc + c] = __floats2half2_rn(acc[mt][nt][0], acc[mt][nt][1]);
                if (mr + 8 < M)
                    *(__half2*)&C[(long)(mr + 8) * Nc + c] = __floats2half2_rn(acc[mt][nt][2], acc[mt][nt][3]);
            } else {
                float* C = (float*)Cv;
                if (mr < M)
                    *(float2*)&C[(long)mr * Nc + c] = make_float2(acc[mt][nt][0], acc[mt][nt][1]);
                if (mr + 8 < M)
                    *(float2*)&C[(long)(mr + 8) * Nc + c] = make_float2(acc[mt][nt][2], acc[mt][nt][3]);
            }
        }
    }

    if (SCORES) {
        const int h = (col0 + wn) >> 5;
#pragma unroll
        for (int mt = 0; mt < MT; mt++) {
            float elA = 0.f, erA = 0.f;
            float elB = 0.f, erB = 0.f;
#pragma unroll
            for (int nt = 0; nt < NT; nt++) {
#pragma unroll
                for (int j = 0; j < 2; j++) {
                    int c = nt * 8 + 2 * t + j;
                    float av = al[h * 32 + c];
                    float rv = ar[h * 32 + c];
                    elA += acc[mt][nt][j] * av;
                    erA += acc[mt][nt][j] * rv;
                    elB += acc[mt][nt][2 + j] * av;
                    erB += acc[mt][nt][2 + j] * rv;
                }
            }
#pragma unroll
            for (int o = 1; o < 4; o <<= 1) {
                elA += __shfl_xor_sync(FULLMASK, elA, o);
                erA += __shfl_xor_sync(FULLMASK, erA, o);
                elB += __shfl_xor_sync(FULLMASK, elB, o);
                erB += __shfl_xor_sync(FULLMASK, erB, o);
            }
            if (t == 0) {
                int r = row0 + wm + mt * 16 + g;
                if (r < M) { el[r * NH + h] = elA; er[r * NH + h] = erA; }
                if (r + 8 < M) { el[(r + 8) * NH + h] = elB; er[(r + 8) * NH + h] = erB; }
            }
        }
    }
}

// ---------------- layer-0 aggregation (×4-unrolled gather, no reductions) ----------------
// warp per dst node; lane l owns dims [l*8, l*8+8) — all within head l/4.
__global__ void k_agg0(const float* __restrict__ b0) {
    __shared__ float swW[8][32 * 9];

    int gt = blockIdx.x * blockDim.x + threadIdx.x;
    int n = gt >> 5, lane = gt & 31;
    int warp = threadIdx.x >> 5;
    if (n >= N_NODES) return;
    int beg = g_rowptr[n], end = g_rowptr[n + 1];
    int deg = end - beg;
    const int hsel = lane >> 2;

    float er[NH0];
    {
        const float4* erp = (const float4*)&g_er0[n * NH0];
        float4 e0 = erp[0], e1 = erp[1];
        er[0] = e0.x; er[1] = e0.y; er[2] = e0.z; er[3] = e0.w;
        er[4] = e1.x; er[5] = e1.y; er[6] = e1.z; er[7] = e1.w;
    }

    float acc[8];
#pragma unroll
    for (int k = 0; k < 8; k++) acc[k] = 0.f;
    float wsum = 0.f;   // per-head total (identical across head quad lanes)

    for (int base = 0; base < deg; base += 32) {
        int i = base + lane;
        int s = 0;                        // pad: row 0 with weight 0
        float w[NH0];
#pragma unroll
        for (int h = 0; h < NH0; h++) w[h] = 0.f;
        if (i < deg) {
            s = g_esrc[beg + i];
            const float4* elp = (const float4*)&g_el0[s * NH0];
            float4 e0 = elp[0], e1 = elp[1];
            float ev[NH0] = {e0.x, e0.y, e0.z, e0.w, e1.x, e1.y, e1.z, e1.w};
#pragma unroll
            for (int h = 0; h < NH0; h++) {
                float e = ev[h] + er[h];
                e = (e > 0.f) ? e : 0.2f * e;
                w[h] = __expf(e);
            }
        }
#pragma unroll
        for (int h = 0; h < NH0; h++) swW[warp][lane * 9 + h] = w[h];
        __syncwarp();

        int cnt = deg - base; if (cnt > 32) cnt = 32;
        int cnt4 = (cnt + 3) & ~3;        // padded lanes have w=0, s=0 (safe)
        for (int j = 0; j < cnt4; j += 4) {
            int s0 = __shfl_sync(FULLMASK, s, j + 0);
            int s1 = __shfl_sync(FULLMASK, s, j + 1);
            int s2 = __shfl_sync(FULLMASK, s, j + 2);
            int s3 = __shfl_sync(FULLMASK, s, j + 3);
            float w0 = swW[warp][(j + 0) * 9 + hsel];
            float w1 = swW[warp][(j + 1) * 9 + hsel];
            float w2 = swW[warp][(j + 2) * 9 + hsel];
            float w3 = swW[warp][(j + 3) * 9 + hsel];
            wsum += (w0 + w1) + (w2 + w3);
            uint4 r0 = *(const uint4*)&g_f0h[s0 * F0 + lane * 8];
            uint4 r1 = *(const uint4*)&g_f0h[s1 * F0 + lane * 8];
            uint4 r2 = *(const uint4*)&g_f0h[s2 * F0 + lane * 8];
            uint4 r3 = *(const uint4*)&g_f0h[s3 * F0 + lane * 8];
#pragma unroll
            for (int q = 0; q < 4; q++) {
                float2 pa = __half22float2(((const __half2*)&r0)[q]);
                acc[2 * q + 0] += w0 * pa.x; acc[2 * q + 1] += w0 * pa.y;
            }
#pragma unroll
            for (int q = 0; q < 4; q++) {
                float2 pa = __half22float2(((const __half2*)&r1)[q]);
                acc[2 * q + 0] += w1 * pa.x; acc[2 * q + 1] += w1 * pa.y;
            }
#pragma unroll
            for (int q = 0; q < 4; q++) {
                float2 pa = __half22float2(((const __half2*)&r2)[q]);
                acc[2 * q + 0] += w2 * pa.x; acc[2 * q + 1] += w2 * pa.y;
            }
#pragma unroll
            for (int q = 0; q < 4; q++) {
                float2 pa = __half22float2(((const __half2*)&r3)[q]);
                acc[2 * q + 0] += w3 * pa.x; acc[2 * q + 1] += w3 * pa.y;
            }
        }
        __syncwarp();
    }

    float inv = (deg > 0) ? (1.f / wsum) : 0.f;

    const float4* bp = (const float4*)&b0[lane * 8];
    float4 b_lo = bp[0], b_hi = bp[1];
    float bb[8] = {b_lo.x, b_lo.y, b_lo.z, b_lo.w, b_hi.x, b_hi.y, b_hi.z, b_hi.w};
    uint4 pack;
    __half2* hp = (__half2*)&pack;
#pragma unroll
    for (int q = 0; q < 4; q++) {
        float t0 = acc[2 * q + 0] * inv + bb[2 * q + 0];
        float t1 = acc[2 * q + 1] * inv + bb[2 * q + 1];
        t0 = (t0 > 0.f) ? t0 : expm1f(t0);
        t1 = (t1 > 0.f) ? t1 : expm1f(t1);
        hp[q] = __floats2half2_rn(t0, t1);
    }
    *(uint4*)&g_hh[n * F0 + lane * 8] = pack;
}

// ---------------- layer-1 aggregation (×4-unrolled, fp16 gather, no reductions) ----------------
__global__ void k_agg1(const float* __restrict__ b1) {
    int g = blockIdx.x * blockDim.x + threadIdx.x;
    int n = g >> 5, lane = g & 31;
    if (n >= N_NODES) return;
    int beg = g_rowptr[n], end = g_rowptr[n + 1];
    int deg = end - beg;
    float er = g_er1[n];

    float acc = 0.f, wsum = 0.f;
    for (int base = 0; base < deg; base += 32) {
        int i = base + lane;
        int s = 0;
        float w = 0.f;
        if (i < deg) {
            s = g_esrc[beg + i];
            float e = g_el1[s] + er;
            e = (e > 0.f) ? e : 0.2f * e;
            w = __expf(e);
        }
        int cnt = deg - base; if (cnt > 32) cnt = 32;
        int cnt4 = (cnt + 3) & ~3;
        for (int j = 0; j < cnt4; j += 4) {
            int s0 = __shfl_sync(FULLMASK, s, j + 0);
            int s1 = __shfl_sync(FULLMASK, s, j + 1);
            int s2 = __shfl_sync(FULLMASK, s, j + 2);
            int s3 = __shfl_sync(FULLMASK, s, j + 3);
            float w0 = __shfl_sync(FULLMASK, w, j + 0);
            float w1 = __shfl_sync(FULLMASK, w, j + 1);
            float w2 = __shfl_sync(FULLMASK, w, j + 2);
            float w3 = __shfl_sync(FULLMASK, w, j + 3);
            wsum += (w0 + w1) + (w2 + w3);
            float f0v = __half2float(g_f1h[s0 * F1 + lane]);
            float f1v = __half2float(g_f1h[s1 * F1 + lane]);
            float f2v = __half2float(g_f1h[s2 * F1 + lane]);
            float f3v = __half2float(g_f1h[s3 * F1 + lane]);
            acc += w0 * f0v + w1 * f1v + w2 * f2v + w3 * f3v;
        }
    }

    float v = (deg > 0) ? (acc / wsum) : 0.f;
    g_h1[n * F1 + lane] = v + b1[lane];
}

// ---------------- link predictor MLP: warp per pair ----------------
__global__ void k_pred(const float* __restrict__ P1, const float* __restrict__ pb1,
                       const float* __restrict__ P2, const float* __restrict__ pb2,
                       const float* __restrict__ P3, const float* __restrict__ pb3,
                       float* __restrict__ out) {
    __shared__ float sP1[1024], sP2[1024], sP3[32], sb1[32], sb2[32];
    for (int i = threadIdx.x; i < 1024; i += blockDim.x) { sP1[i] = P1[i]; sP2[i] = P2[i]; }
    if (threadIdx.x < 32) {
        sP3[threadIdx.x] = P3[threadIdx.x];
        sb1[threadIdx.x] = pb1[threadIdx.x];
        sb2[threadIdx.x] = pb2[threadIdx.x];
    }
    __syncthreads();

    int g = blockIdx.x * blockDim.x + threadIdx.x;
    int w = g >> 5, lane = g & 31;
    if (w >= 2 * NE_PAIRS) return;
    int neg = (w >= NE_PAIRS) ? 1 : 0;
    int i = w - neg * NE_PAIRS;

    float a = g_h1[i * F1 + lane];
    int dst_row = neg ? (2 * NE_PAIRS + i) : (NE_PAIRS + i);
    float z = a * g_h1[dst_row * F1 + lane];

    float y = sb1[lane];
#pragma unroll
    for (int d = 0; d < 32; d++) {
        float zd = __shfl_sync(FULLMASK, z, d);
        y += zd * sP1[d * 32 + lane];
    }
    y = fmaxf(y, 0.f);
    float y2 = sb2[lane];
#pragma unroll
    for (int d = 0; d < 32; d++) {
        float yd = __shfl_sync(FULLMASK, y, d);
        y2 += yd * sP2[d * 32 + lane];
    }
    y2 = fmaxf(y2, 0.f);
    float t = y2 * sP3[lane];
#pragma unroll
    for (int o = 16; o; o >>= 1) t += __shfl_xor_sync(FULLMASK, t, o);
    if (lane == 0) out[neg * NE_PAIRS + i] = t + pb3[0];
}

// ---------------- launch ----------------
extern "C" void kernel_launch(void* const* d_in, const int* in_sizes, int n_in,
                              void* d_out, int out_size) {
    const float* x   = (const float*)d_in[0];
    const int*   src = (const int*)d_in[1];
    const int*   dst = (const int*)d_in[2];
    const float* W0  = (const float*)d_in[4];
    const float* al0 = (const float*)d_in[5];
    const float* ar0 = (const float*)d_in[6];
    const float* b0  = (const float*)d_in[7];
    const float* W1  = (const float*)d_in[8];
    const float* al1 = (const float*)d_in[9];
    const float* ar1 = (const float*)d_in[10];
    const float* b1  = (const float*)d_in[11];
    const float* P1  = (const float*)d_in[12];
    const float* pb1 = (const float*)d_in[13];
    const float* P2  = (const float*)d_in[14];
    const float* pb2 = (const float*)d_in[15];
    const float* P3  = (const float*)d_in[16];
    const float* pb3 = (const float*)d_in[17];
    float* out = (float*)d_out;

    void *p_f0h, *p_f1h, *p_hh;
    float *p_el0, *p_er0, *p_el1, *p_er1;
    cudaGetSymbolAddress(&p_f0h, g_f0h);
    cudaGetSymbolAddress(&p_f1h, g_f1h);
    cudaGetSymbolAddress(&p_hh, g_hh);
    cudaGetSymbolAddress((void**)&p_el0, g_el0);
    cudaGetSymbolAddress((void**)&p_er0, g_er0);
    cudaGetSymbolAddress((void**)&p_el1, g_el1);
    cudaGetSymbolAddress((void**)&p_er1, g_er1);

    static cudaStream_t sB = nullptr;
    static cudaEvent_t evFork = nullptr, evJoin = nullptr;
    if (sB == nullptr) {
        cudaStreamCreateWithFlags(&sB, cudaStreamNonBlocking);
        cudaEventCreateWithFlags(&evFork, cudaEventDisableTiming);
        cudaEventCreateWithFlags(&evJoin, cudaEventDisableTiming);
    }

    cudaEventRecord(evFork, 0);
    cudaStreamWaitEvent(sB, evFork, 0);

    // branch B: CSR by dst
    k_zero_cnt<<<(N_NODES + 255) / 256, 256, 0, sB>>>();
    k_count<<<(E_EDGES + 255) / 256, 256, 0, sB>>>(dst);
    k_scan<<<1, 1024, 0, sB>>>();
    k_fill<<<(E_EDGES + 255) / 256, 256, 0, sB>>>(src, dst);
    cudaEventRecord(evJoin, sB);

    // branch A: layer-0 GEMM (pipelined tf32) + fused scores, fp16 out
    // BM=128, BN=64, BK=16, WM=64, WN=32 -> 128 threads, MT=4, NT=4
    k_gemm<128, 64, 16, 64, 32, NH0, true, false, true>
        <<<dim3(F0 / 64, (N_NODES + 127) / 128), 128>>>(
            x, W0, p_f0h, N_NODES, F0, DIN, al0, ar0, p_el0, p_er0);

    cudaStreamWaitEvent(0, evJoin, 0);

    k_agg0<<<(N_NODES + 7) / 8, 256>>>(b0);

    // layer 1: pipelined tf32 GEMM, fp16 A (g_hh), fp16 out, fused scores
    // BM=128, BN=32, BK=16, WM=32, WN=32 -> 128 threads, MT=2, NT=4
    k_gemm<128, 32, 16, 32, 32, 1, true, true, true>
        <<<dim3(1, (N_NODES + 127) / 128), 128>>>(
            p_hh, W1, p_f1h, N_NODES, F1, F0, al1, ar1, p_el1, p_er1);
    k_agg1<<<(N_NODES * 32 + 255) / 256, 256>>>(b1);

    // predictor
    k_pred<<<(2 * NE_PAIRS * 32 + 255) / 256, 256>>>(P1, pb1, P2, pb2, P3, pb3, out);
}

// round 12
// speedup vs baseline: 1.5097x; 1.5097x over previous
#include <cuda_runtime.h>
#include <cuda_fp16.h>
#include <math.h>
#include <stdint.h>

#define N_NODES 49998
#define E_EDGES 800000
#define DIN 128
#define NH0 8
#define DOUT 32
#define F0 (NH0 * DOUT)   // 256
#define F1 32
#define NE_PAIRS (N_NODES / 3)  // 16666
#define FULLMASK 0xffffffffu
#define SCAN_BLOCKS ((N_NODES + 1023) / 1024)   // 49

// ---------------- scratch (device globals: no runtime alloc allowed) ----------------
__device__ __half g_f0h[N_NODES * F0];   // layer0 projected features (fp16)
__device__ __half g_hh[N_NODES * F0];    // elu(gat0 out) (fp16)
__device__ float g_el0[N_NODES * NH0];
__device__ float g_er0[N_NODES * NH0];
__device__ __half g_f1h[N_NODES * F1];   // layer1 projected features (fp16)
__device__ float g_el1[N_NODES];
__device__ float g_er1[N_NODES];
__device__ float g_h1[N_NODES * F1];
__device__ int   g_cnt[N_NODES];
__device__ int   g_rowptr[N_NODES + 1];
__device__ int   g_cur[N_NODES];
__device__ int   g_esrc[E_EDGES];
__device__ int   g_bsum[64];
__device__ int   g_boff[64];

// ---------------- CSR build ----------------
// 8 edges per thread, int4 loads (MLP=8)
__global__ void k_count(const int* __restrict__ dst) {
    int t = blockIdx.x * blockDim.x + threadIdx.x;
    if (t * 8 >= E_EDGES) return;
    const int4* d4 = (const int4*)dst;
    int4 a = d4[t * 2], b = d4[t * 2 + 1];
    atomicAdd(&g_cnt[a.x], 1); atomicAdd(&g_cnt[a.y], 1);
    atomicAdd(&g_cnt[a.z], 1); atomicAdd(&g_cnt[a.w], 1);
    atomicAdd(&g_cnt[b.x], 1); atomicAdd(&g_cnt[b.y], 1);
    atomicAdd(&g_cnt[b.z], 1); atomicAdd(&g_cnt[b.w], 1);
}

// block-level exclusive scan (coalesced), writes local scan + block sums
__global__ void k_scan1() {
    int i = blockIdx.x * 1024 + threadIdx.x;
    int v = (i < N_NODES) ? g_cnt[i] : 0;
    int lane = threadIdx.x & 31, wid = threadIdx.x >> 5;
    int x = v;
#pragma unroll
    for (int o = 1; o < 32; o <<= 1) {
        int y = __shfl_up_sync(FULLMASK, x, o);
        if (lane >= o) x += y;
    }
    __shared__ int wsum[32];
    if (lane == 31) wsum[wid] = x;
    __syncthreads();
    if (wid == 0) {
        int y = wsum[lane];
#pragma unroll
        for (int o = 1; o < 32; o <<= 1) {
            int z = __shfl_up_sync(FULLMASK, y, o);
            if (lane >= o) y += z;
        }
        wsum[lane] = y;
    }
    __syncthreads();
    int excl = x - v + (wid > 0 ? wsum[wid - 1] : 0);
    if (i < N_NODES) g_rowptr[i] = excl;       // block-local exclusive
    if (threadIdx.x == 0) g_bsum[blockIdx.x] = wsum[31];
}

// scan the 49 block sums (64 threads)
__global__ void k_scan2() {
    const int NB = SCAN_BLOCKS;
    int tid = threadIdx.x;
    int v = (tid < NB) ? g_bsum[tid] : 0;
    int lane = tid & 31, w = tid >> 5;
    int x = v;
#pragma unroll
    for (int o = 1; o < 32; o <<= 1) {
        int y = __shfl_up_sync(FULLMASK, x, o);
        if (lane >= o) x += y;
    }
    __shared__ int ws[2];
    if (lane == 31) ws[w] = x;
    __syncthreads();
    if (w == 1) x += ws[0];
    if (tid < NB) g_boff[tid] = x - v;
    if (tid == NB - 1) g_rowptr[N_NODES] = x;
}

// add block offsets, emit cursor copy
__global__ void k_scan3() {
    int i = blockIdx.x * 1024 + threadIdx.x;
    if (i < N_NODES) {
        int r = g_rowptr[i] + g_boff[blockIdx.x];
        g_rowptr[i] = r;
        g_cur[i] = r;
    }
}

__global__ void k_fill(const int* __restrict__ src, const int* __restrict__ dst) {
    int t = blockIdx.x * blockDim.x + threadIdx.x;
    if (t * 8 >= E_EDGES) return;
    const int4* d4 = (const int4*)dst;
    const int4* s4 = (const int4*)src;
    int4 da = d4[t * 2], db = d4[t * 2 + 1];
    int4 sa = s4[t * 2], sb = s4[t * 2 + 1];
    int p;
    p = atomicAdd(&g_cur[da.x], 1); g_esrc[p] = sa.x;
    p = atomicAdd(&g_cur[da.y], 1); g_esrc[p] = sa.y;
    p = atomicAdd(&g_cur[da.z], 1); g_esrc[p] = sa.z;
    p = atomicAdd(&g_cur[da.w], 1); g_esrc[p] = sa.w;
    p = atomicAdd(&g_cur[db.x], 1); g_esrc[p] = sb.x;
    p = atomicAdd(&g_cur[db.y], 1); g_esrc[p] = sb.y;
    p = atomicAdd(&g_cur[db.z], 1); g_esrc[p] = sb.z;
    p = atomicAdd(&g_cur[db.w], 1); g_esrc[p] = sb.w;
}

// ---------------- tf32 tensor-core GEMM + fused attention scores ----------------
__device__ __forceinline__ uint32_t f2tf(float f) {
    uint32_t r;
    asm("cvt.rna.tf32.f32 %0, %1;" : "=r"(r) : "f"(f));
    return r;
}

__device__ __forceinline__ void mma_tf32(float* d, const uint32_t* a, const uint32_t* b) {
    asm volatile(
        "mma.sync.aligned.m16n8k8.row.col.f32.tf32.tf32.f32 "
        "{%0,%1,%2,%3},{%4,%5,%6,%7},{%8,%9},{%0,%1,%2,%3};\n"
        : "+f"(d[0]), "+f"(d[1]), "+f"(d[2]), "+f"(d[3])
        : "r"(a[0]), "r"(a[1]), "r"(a[2]), "r"(a[3]), "r"(b[0]), "r"(b[1]));
}

// C(MxNc) = A(MxK) @ B(KxNc), tf32 inputs, fp32 accumulate (R10 structure).
// HALF_IN: A is __half. HALF_OUT: C stored as __half. SCORES needs WN==32.
template <int BM, int BN, int BK, int WM, int WN, int NH,
          bool SCORES, bool HALF_IN, bool HALF_OUT>
__global__ void k_gemm_tf32(const void* __restrict__ Av, const float* __restrict__ B,
                            void* __restrict__ Cv, int M, int Nc, int K,
                            const float* __restrict__ al, const float* __restrict__ ar,
                            float* __restrict__ el, float* __restrict__ er) {
    constexpr int WARPS_M = BM / WM;
    constexpr int WARPS_N = BN / WN;
    constexpr int THREADS = WARPS_M * WARPS_N * 32;
    constexpr int MT = WM / 16;
    constexpr int NT = WN / 8;
    constexpr int AP = BK + 4;
    constexpr int BP = BN + 8;

    __shared__ uint32_t As[BM][AP];
    __shared__ uint32_t Bs[BK][BP];

    const int tid = threadIdx.x;
    const int wid = tid >> 5, lane = tid & 31;
    const int wm = (wid / WARPS_N) * WM;
    const int wn = (wid % WARPS_N) * WN;
    const int g = lane >> 2, t = lane & 3;
    const int row0 = blockIdx.y * BM, col0 = blockIdx.x * BN;

    float acc[MT][NT][4];
#pragma unroll
    for (int mt = 0; mt < MT; mt++)
#pragma unroll
        for (int nt = 0; nt < NT; nt++)
#pragma unroll
            for (int j = 0; j < 4; j++) acc[mt][nt][j] = 0.f;

    constexpr int A_CG = BK / 4;
    constexpr int A_RPP = THREADS / A_CG;
    constexpr int NB4 = BN / 4;
    constexpr int B_RPP = THREADS / NB4;

    for (int k0 = 0; k0 < K; k0 += BK) {
#pragma unroll
        for (int i = 0; i < BM / A_RPP; i++) {
            int r = (tid / A_CG) + i * A_RPP;
            int c = (tid % A_CG) * 4;
            int gr = row0 + r;
            float vx = 0.f, vy = 0.f, vz = 0.f, vw = 0.f;
            if (HALF_IN) {
                if (gr < M) {
                    uint2 v = *(const uint2*)((const __half*)Av + (long)gr * K + k0 + c);
                    float2 x0 = __half22float2(*(__half2*)&v.x);
                    float2 x1 = __half22float2(*(__half2*)&v.y);
                    vx = x0.x; vy = x0.y; vz = x1.x; vw = x1.y;
                }
            } else {
                if (gr < M) {
                    float4 v = *(const float4*)((const float*)Av + (long)gr * K + k0 + c);
                    vx = v.x; vy = v.y; vz = v.z; vw = v.w;
                }
            }
            As[r][c + 0] = f2tf(vx);
            As[r][c + 1] = f2tf(vy);
            As[r][c + 2] = f2tf(vz);
            As[r][c + 3] = f2tf(vw);
        }
#pragma unroll
        for (int i = 0; i < BK / B_RPP; i++) {
            int r = tid / NB4 + i * B_RPP;
            int c = (tid % NB4) * 4;
            float4 v = *(const float4*)&B[(long)(k0 + r) * Nc + col0 + c];
            Bs[r][c + 0] = f2tf(v.x);
            Bs[r][c + 1] = f2tf(v.y);
            Bs[r][c + 2] = f2tf(v.z);
            Bs[r][c + 3] = f2tf(v.w);
        }
        __syncthreads();

#pragma unroll
        for (int ks = 0; ks < BK / 8; ks++) {
            const int k8 = ks * 8;
            uint32_t af[MT][4], bf[NT][2];
#pragma unroll
            for (int mt = 0; mt < MT; mt++) {
                int r = wm + mt * 16;
                af[mt][0] = As[r + g][k8 + t];
                af[mt][1] = As[r + g + 8][k8 + t];
                af[mt][2] = As[r + g][k8 + t + 4];
                af[mt][3] = As[r + g + 8][k8 + t + 4];
            }
#pragma unroll
            for (int nt = 0; nt < NT; nt++) {
                int c = wn + nt * 8 + g;
                bf[nt][0] = Bs[k8 + t][c];
                bf[nt][1] = Bs[k8 + t + 4][c];
            }
#pragma unroll
            for (int mt = 0; mt < MT; mt++)
#pragma unroll
                for (int nt = 0; nt < NT; nt++) mma_tf32(acc[mt][nt], af[mt], bf[nt]);
        }
        __syncthreads();
    }

#pragma unroll
    for (int mt = 0; mt < MT; mt++) {
#pragma unroll
        for (int nt = 0; nt < NT; nt++) {
            int mr = row0 + wm + mt * 16 + g;
            int c = col0 + wn + nt * 8 + 2 * t;
            if (HALF_OUT) {
                __half* C = (__half*)Cv;
                if (mr < M)
                    *(__half2*)&C[(long)mr * Nc + c] = __floats2half2_rn(acc[mt][nt][0], acc[mt][nt][1]);
                if (mr + 8 < M)
                    *(__half2*)&C[(long)(mr + 8) * Nc + c] = __floats2half2_rn(acc[mt][nt][2], acc[mt][nt][3]);
            } else {
                float* C = (float*)Cv;
                if (mr < M)
                    *(float2*)&C[(long)mr * Nc + c] = make_float2(acc[mt][nt][0], acc[mt][nt][1]);
                if (mr + 8 < M)
                    *(float2*)&C[(long)(mr + 8) * Nc + c] = make_float2(acc[mt][nt][2], acc[mt][nt][3]);
            }
        }
    }

    if (SCORES) {
        const int h = (col0 + wn) >> 5;
#pragma unroll
        for (int mt = 0; mt < MT; mt++) {
            float elA = 0.f, erA = 0.f;
            float elB = 0.f, erB = 0.f;
#pragma unroll
            for (int nt = 0; nt < NT; nt++) {
#pragma unroll
                for (int j = 0; j < 2; j++) {
                    int c = nt * 8 + 2 * t + j;
                    float av = al[h * 32 + c];
                    float rv = ar[h * 32 + c];
                    elA += acc[mt][nt][j] * av;
                    erA += acc[mt][nt][j] * rv;
                    elB += acc[mt][nt][2 + j] * av;
                    erB += acc[mt][nt][2 + j] * rv;
                }
            }
#pragma unroll
            for (int o = 1; o < 4; o <<= 1) {
                elA += __shfl_xor_sync(FULLMASK, elA, o);
                erA += __shfl_xor_sync(FULLMASK, erA, o);
                elB += __shfl_xor_sync(FULLMASK, elB, o);
                erB += __shfl_xor_sync(FULLMASK, erB, o);
            }
            if (t == 0) {
                int r = row0 + wm + mt * 16 + g;
                if (r < M) { el[r * NH + h] = elA; er[r * NH + h] = erA; }
                if (r + 8 < M) { el[(r + 8) * NH + h] = elB; er[(r + 8) * NH + h] = erB; }
            }
        }
    }
}

// ---------------- layer-0 aggregation: 2 warps per node ----------------
// warp half w owns heads [4w,4w+4) / dims [128w,128w+128); lane owns 4 dims.
__global__ void k_agg0(const float* __restrict__ b0) {
    __shared__ float swW[8][32 * 5];   // [warp-in-block][edge*5 + head(0..3)]

    int gt = blockIdx.x * blockDim.x + threadIdx.x;
    int gw = gt >> 5, lane = gt & 31;
    int warp = threadIdx.x >> 5;
    int n = gw >> 1, half = gw & 1;
    if (n >= N_NODES) return;
    int beg = g_rowptr[n], end = g_rowptr[n + 1];
    int deg = end - beg;
    const int hsel = lane >> 3;        // head within our 4

    float4 er4 = *(const float4*)&g_er0[n * NH0 + half * 4];
    float er[4] = {er4.x, er4.y, er4.z, er4.w};

    float acc[4] = {0.f, 0.f, 0.f, 0.f};
    float wsum = 0.f;                  // per-head total (identical across 8-lane groups)

    for (int base = 0; base < deg; base += 32) {
        int i = base + lane;
        int s = 0;                      // pad: row 0 with weight 0
        float w[4] = {0.f, 0.f, 0.f, 0.f};
        if (i < deg) {
            s = g_esrc[beg + i];
            float4 el4 = *(const float4*)&g_el0[s * NH0 + half * 4];
            float ev[4] = {el4.x, el4.y, el4.z, el4.w};
#pragma unroll
            for (int h = 0; h < 4; h++) {
                float e = ev[h] + er[h];
                e = (e > 0.f) ? e : 0.2f * e;
                w[h] = __expf(e);
            }
        }
#pragma unroll
        for (int h = 0; h < 4; h++) swW[warp][lane * 5 + h] = w[h];
        __syncwarp();

        int cnt = deg - base; if (cnt > 32) cnt = 32;
        int cnt4 = (cnt + 3) & ~3;      // padded lanes have w=0, s=0 (safe)
        for (int j = 0; j < cnt4; j += 4) {
            int s0 = __shfl_sync(FULLMASK, s, j + 0);
            int s1 = __shfl_sync(FULLMASK, s, j + 1);
            int s2 = __shfl_sync(FULLMASK, s, j + 2);
            int s3 = __shfl_sync(FULLMASK, s, j + 3);
            float w0 = swW[warp][(j + 0) * 5 + hsel];
            float w1 = swW[warp][(j + 1) * 5 + hsel];
            float w2 = swW[warp][(j + 2) * 5 + hsel];
            float w3 = swW[warp][(j + 3) * 5 + hsel];
            wsum += (w0 + w1) + (w2 + w3);
            uint2 r0 = *(const uint2*)&g_f0h[s0 * F0 + half * 128 + lane * 4];
            uint2 r1 = *(const uint2*)&g_f0h[s1 * F0 + half * 128 + lane * 4];
            uint2 r2 = *(const uint2*)&g_f0h[s2 * F0 + half * 128 + lane * 4];
            uint2 r3 = *(const uint2*)&g_f0h[s3 * F0 + half * 128 + lane * 4];
            {
                float2 a0 = __half22float2(*(__half2*)&r0.x);
                float2 a1 = __half22float2(*(__half2*)&r0.y);
                acc[0] += w0 * a0.x; acc[1] += w0 * a0.y;
                acc[2] += w0 * a1.x; acc[3] += w0 * a1.y;
            }
            {
                float2 a0 = __half22float2(*(__half2*)&r1.x);
                float2 a1 = __half22float2(*(__half2*)&r1.y);
                acc[0] += w1 * a0.x; acc[1] += w1 * a0.y;
                acc[2] += w1 * a1.x; acc[3] += w1 * a1.y;
            }
            {
                float2 a0 = __half22float2(*(__half2*)&r2.x);
                float2 a1 = __half22float2(*(__half2*)&r2.y);
                acc[0] += w2 * a0.x; acc[1] += w2 * a0.y;
                acc[2] += w2 * a1.x; acc[3] += w2 * a1.y;
            }
            {
                float2 a0 = __half22float2(*(__half2*)&r3.x);
                float2 a1 = __half22float2(*(__half2*)&r3.y);
                acc[0] += w3 * a0.x; acc[1] += w3 * a0.y;
                acc[2] += w3 * a1.x; acc[3] += w3 * a1.y;
            }
        }
        __syncwarp();
    }

    float inv = (deg > 0) ? (1.f / wsum) : 0.f;

    float4 b4 = *(const float4*)&b0[half * 128 + lane * 4];
    float bb[4] = {b4.x, b4.y, b4.z, b4.w};
    uint2 pack;
    __half2* hp = (__half2*)&pack;
#pragma unroll
    for (int q = 0; q < 2; q++) {
        float t0 = acc[2 * q + 0] * inv + bb[2 * q + 0];
        float t1 = acc[2 * q + 1] * inv + bb[2 * q + 1];
        t0 = (t0 > 0.f) ? t0 : expm1f(t0);
        t1 = (t1 > 0.f) ? t1 : expm1f(t1);
        hp[q] = __floats2half2_rn(t0, t1);
    }
    *(uint2*)&g_hh[n * F0 + half * 128 + lane * 4] = pack;
}

// ---------------- layer-1 aggregation (×4-unrolled, fp16 gather) ----------------
__global__ void k_agg1(const float* __restrict__ b1) {
    int g = blockIdx.x * blockDim.x + threadIdx.x;
    int n = g >> 5, lane = g & 31;
    if (n >= N_NODES) return;
    int beg = g_rowptr[n], end = g_rowptr[n + 1];
    int deg = end - beg;
    float er = g_er1[n];

    float acc = 0.f, wsum = 0.f;
    for (int base = 0; base < deg; base += 32) {
        int i = base + lane;
        int s = 0;
        float w = 0.f;
        if (i < deg) {
            s = g_esrc[beg + i];
            float e = g_el1[s] + er;
            e = (e > 0.f) ? e : 0.2f * e;
            w = __expf(e);
        }
        int cnt = deg - base; if (cnt > 32) cnt = 32;
        int cnt4 = (cnt + 3) & ~3;
        for (int j = 0; j < cnt4; j += 4) {
            int s0 = __shfl_sync(FULLMASK, s, j + 0);
            int s1 = __shfl_sync(FULLMASK, s, j + 1);
            int s2 = __shfl_sync(FULLMASK, s, j + 2);
            int s3 = __shfl_sync(FULLMASK, s, j + 3);
            float w0 = __shfl_sync(FULLMASK, w, j + 0);
            float w1 = __shfl_sync(FULLMASK, w, j + 1);
            float w2 = __shfl_sync(FULLMASK, w, j + 2);
            float w3 = __shfl_sync(FULLMASK, w, j + 3);
            wsum += (w0 + w1) + (w2 + w3);
            float f0v = __half2float(g_f1h[s0 * F1 + lane]);
            float f1v = __half2float(g_f1h[s1 * F1 + lane]);
            float f2v = __half2float(g_f1h[s2 * F1 + lane]);
            float f3v = __half2float(g_f1h[s3 * F1 + lane]);
            acc += w0 * f0v + w1 * f1v + w2 * f2v + w3 * f3v;
        }
    }

    float v = (deg > 0) ? (acc / wsum) : 0.f;
    g_h1[n * F1 + lane] = v + b1[lane];
}

// ---------------- link predictor MLP: warp per pair ----------------
__global__ void k_pred(const float* __restrict__ P1, const float* __restrict__ pb1,
                       const float* __restrict__ P2, const float* __restrict__ pb2,
                       const float* __restrict__ P3, const float* __restrict__ pb3,
                       float* __restrict__ out) {
    __shared__ float sP1[1024], sP2[1024], sP3[32], sb1[32], sb2[32];
    for (int i = threadIdx.x; i < 1024; i += blockDim.x) { sP1[i] = P1[i]; sP2[i] = P2[i]; }
    if (threadIdx.x < 32) {
        sP3[threadIdx.x] = P3[threadIdx.x];
        sb1[threadIdx.x] = pb1[threadIdx.x];
        sb2[threadIdx.x] = pb2[threadIdx.x];
    }
    __syncthreads();

    int g = blockIdx.x * blockDim.x + threadIdx.x;
    int w = g >> 5, lane = g & 31;
    if (w >= 2 * NE_PAIRS) return;
    int neg = (w >= NE_PAIRS) ? 1 : 0;
    int i = w - neg * NE_PAIRS;

    float a = g_h1[i * F1 + lane];
    int dst_row = neg ? (2 * NE_PAIRS + i) : (NE_PAIRS + i);
    float z = a * g_h1[dst_row * F1 + lane];

    float y = sb1[lane];
#pragma unroll
    for (int d = 0; d < 32; d++) {
        float zd = __shfl_sync(FULLMASK, z, d);
        y += zd * sP1[d * 32 + lane];
    }
    y = fmaxf(y, 0.f);
    float y2 = sb2[lane];
#pragma unroll
    for (int d = 0; d < 32; d++) {
        float yd = __shfl_sync(FULLMASK, y, d);
        y2 += yd * sP2[d * 32 + lane];
    }
    y2 = fmaxf(y2, 0.f);
    float t = y2 * sP3[lane];
#pragma unroll
    for (int o = 16; o; o >>= 1) t += __shfl_xor_sync(FULLMASK, t, o);
    if (lane == 0) out[neg * NE_PAIRS + i] = t + pb3[0];
}

// ---------------- launch ----------------
extern "C" void kernel_launch(void* const* d_in, const int* in_sizes, int n_in,
                              void* d_out, int out_size) {
    const float* x   = (const float*)d_in[0];
    const int*   src = (const int*)d_in[1];
    const int*   dst = (const int*)d_in[2];
    const float* W0  = (const float*)d_in[4];
    const float* al0 = (const float*)d_in[5];
    const float* ar0 = (const float*)d_in[6];
    const float* b0  = (const float*)d_in[7];
    const float* W1  = (const float*)d_in[8];
    const float* al1 = (const float*)d_in[9];
    const float* ar1 = (const float*)d_in[10];
    const float* b1  = (const float*)d_in[11];
    const float* P1  = (const float*)d_in[12];
    const float* pb1 = (const float*)d_in[13];
    const float* P2  = (const float*)d_in[14];
    const float* pb2 = (const float*)d_in[15];
    const float* P3  = (const float*)d_in[16];
    const float* pb3 = (const float*)d_in[17];
    float* out = (float*)d_out;

    void *p_f0h, *p_f1h, *p_hh, *p_cnt;
    float *p_el0, *p_er0, *p_el1, *p_er1;
    cudaGetSymbolAddress(&p_f0h, g_f0h);
    cudaGetSymbolAddress(&p_f1h, g_f1h);
    cudaGetSymbolAddress(&p_hh, g_hh);
    cudaGetSymbolAddress(&p_cnt, g_cnt);
    cudaGetSymbolAddress((void**)&p_el0, g_el0);
    cudaGetSymbolAddress((void**)&p_er0, g_er0);
    cudaGetSymbolAddress((void**)&p_el1, g_el1);
    cudaGetSymbolAddress((void**)&p_er1, g_er1);

    static cudaStream_t sB = nullptr;
    static cudaEvent_t evFork = nullptr, evJoin = nullptr;
    if (sB == nullptr) {
        cudaStreamCreateWithFlags(&sB, cudaStreamNonBlocking);
        cudaEventCreateWithFlags(&evFork, cudaEventDisableTiming);
        cudaEventCreateWithFlags(&evJoin, cudaEventDisableTiming);
    }

    cudaEventRecord(evFork, 0);
    cudaStreamWaitEvent(sB, evFork, 0);

    // branch B: CSR by dst (memset + 8-edges/thread count/fill + parallel scan)
    cudaMemsetAsync(p_cnt, 0, N_NODES * sizeof(int), sB);
    k_count<<<(E_EDGES / 8 + 255) / 256, 256, 0, sB>>>(dst);
    k_scan1<<<SCAN_BLOCKS, 1024, 0, sB>>>();
    k_scan2<<<1, 64, 0, sB>>>();
    k_scan3<<<SCAN_BLOCKS, 1024, 0, sB>>>();
    k_fill<<<(E_EDGES / 8 + 255) / 256, 256, 0, sB>>>(src, dst);
    cudaEventRecord(evJoin, sB);

    // branch A: layer-0 GEMM (tf32) + fused scores, fp16 out
    k_gemm_tf32<128, 64, 32, 32, 32, NH0, true, false, true>
        <<<dim3(F0 / 64, (N_NODES + 127) / 128), 256>>>(
            x, W0, p_f0h, N_NODES, F0, DIN, al0, ar0, p_el0, p_er0);

    cudaStreamWaitEvent(0, evJoin, 0);

    // 2 warps per node
    k_agg0<<<(2 * N_NODES + 7) / 8, 256>>>(b0);

    // layer 1: tf32 GEMM, fp16 in (g_hh), fp16 out, fused scores
    k_gemm_tf32<128, 32, 32, 16, 32, 1, true, true, true>
        <<<dim3(1, (N_NODES + 127) / 128), 256>>>(
            p_hh, W1, p_f1h, N_NODES, F1, F0, al1, ar1, p_el1, p_er1);
    k_agg1<<<(N_NODES * 32 + 255) / 256, 256>>>(b1);

    // predictor
    k_pred<<<(2 * NE_PAIRS * 32 + 255) / 256, 256>>>(P1, pb1, P2, pb2, P3, pb3, out);
}